// round 9
// baseline (speedup 1.0000x reference)
#include <cuda_runtime.h>
#include <cstdint>

#define N_DENSE    64
#define N_SAMPLES  121
#define N_CHANNELS 384
#define BATCH      2048
#define ROW_IN     (N_DENSE * (1 + N_SAMPLES))   // 7808 floats per input row
#define ROW_OUT    (N_CHANNELS * N_SAMPLES)      // 46464 floats per output batch
#define N_VEC      (ROW_OUT / 4)                 // 11616 float4 per batch row
#define DATA_F     (N_DENSE * N_SAMPLES)         // 7744 floats of sample data
#define NTHREADS   320                           // 10 warps -> 6 CTAs/SM (60/64 warps)

__device__ __forceinline__ void cp16(float* dst_smem, const float4* src) {
    uint32_t d = (uint32_t)__cvta_generic_to_shared(dst_smem);
    asm volatile("cp.async.cg.shared.global [%0], [%1], 16;\n" :: "r"(d), "l"(src));
}

// One CTA per batch row; smem-staged data tile (cp.async), shared-memory
// inverted index, flat vec4 output mapping with incremental (c,s), two-walk
// straddle handling, streaming STG.128. 320 threads -> 6 CTAs/SM for finer
// wave granularity at the HBM write ceiling.
__global__ __launch_bounds__(NTHREADS)
void sparse_input_gather_v9(const float* __restrict__ in,
                            float* __restrict__ out)
{
    __shared__ float sdata[DATA_F + 4];   // staged [64][121]
    __shared__ int   head[N_CHANNELS];
    __shared__ int   nxt[N_DENSE];

    const int b = blockIdx.x;
    const int t = threadIdx.x;

    const float* __restrict__ row  = in + (size_t)b * ROW_IN;
    const float* __restrict__ data = row + N_DENSE;

    // ---- phase 1: async-stage data, build inverted index ----
    int my_c = -1;
    if (t < N_DENSE) {
        int c = (int)__ldg(&row[t]);
        my_c = max(0, min(N_CHANNELS - 1, c));
    }
    #pragma unroll
    for (int i = t; i < N_CHANNELS; i += NTHREADS) head[i] = -1;

    {
        const float4* __restrict__ src = reinterpret_cast<const float4*>(data);
        #pragma unroll
        for (int i = t; i < DATA_F / 4; i += NTHREADS)   // 1936 vec4, fire-and-forget
            cp16(&sdata[4 * i], &src[i]);
        asm volatile("cp.async.commit_group;\n" ::: "memory");
    }
    __syncthreads();                       // head[] init visible
    if (t < N_DENSE)
        nxt[t] = atomicExch(&head[my_c], t);
    asm volatile("cp.async.wait_group 0;\n" ::: "memory");
    __syncthreads();                       // sdata + chains visible

    // ---- phase 2: gather ----
    float4* __restrict__ ovec = reinterpret_cast<float4*>(out + (size_t)b * ROW_OUT);

    // (c, s) for p = 4t; stride NTHREADS vec4 = 1280 floats = 10*121 + 70
    int c = (4 * t) / N_SAMPLES;
    int s = 4 * t - c * N_SAMPLES;

    #pragma unroll 4
    for (int v = t; v < N_VEC; v += NTHREADS) {
        float4 acc = make_float4(0.f, 0.f, 0.f, 0.f);

        if (s <= N_SAMPLES - 4) {
            // fast path: all 4 samples in channel c (~85% of chains empty)
            int d = head[c];
            while (d >= 0) {
                const float* g = sdata + d * N_SAMPLES + s;
                acc.x += g[0];
                acc.y += g[1];
                acc.z += g[2];
                acc.w += g[3];
                d = nxt[d];
            }
        } else {
            // straddle: nA = 121 - s in {1,2,3} samples from c, rest from c+1
            const int nA = N_SAMPLES - s;
            int d = head[c];
            while (d >= 0) {                           // walk A: channel c
                const float* g = sdata + d * N_SAMPLES + s;
                acc.x += g[0];
                if (nA > 1) acc.y += g[1];
                if (nA > 2) acc.z += g[2];
                d = nxt[d];
            }
            int d2 = head[c + 1];
            while (d2 >= 0) {                          // walk B: channel c+1
                const float* g2 = sdata + d2 * N_SAMPLES - nA;  // + j, j in [nA,3]
                if (nA < 2) acc.y += g2[1];
                if (nA < 3) acc.z += g2[2];
                acc.w += g2[3];
                d2 = nxt[d2];
            }
        }
        __stcs(&ovec[v], acc);          // streaming 128-bit store

        // advance (c, s) by 1280 flat elements: c += 10, s += 70, wrap
        s += 70; c += 10;
        if (s >= N_SAMPLES) { s -= N_SAMPLES; c++; }
    }
}

extern "C" void kernel_launch(void* const* d_in, const int* in_sizes, int n_in,
                              void* d_out, int out_size)
{
    const float* in  = (const float*)d_in[0];
    float*       out = (float*)d_out;
    sparse_input_gather_v9<<<BATCH, NTHREADS>>>(in, out);
}

// round 10
// speedup vs baseline: 1.0329x; 1.0329x over previous
#include <cuda_runtime.h>
#include <cstdint>

#define N_DENSE    64
#define N_SAMPLES  121
#define N_CHANNELS 384
#define BATCH      2048
#define ROW_IN     (N_DENSE * (1 + N_SAMPLES))   // 7808 floats per input row
#define ROW_OUT    (N_CHANNELS * N_SAMPLES)      // 46464 floats per output batch
#define N_VEC      (ROW_OUT / 4)                 // 11616 float4 per batch row
#define DATA_F     (N_DENSE * N_SAMPLES)         // 7744 floats of sample data
#define NTHREADS   384                           // 12 warps -> 5 CTAs/SM

// Final kernel (v6 configuration — best measured point on the HBM write
// plateau). One CTA per batch row:
//   phase 1: stage the 31KB data tile in smem (float4 copy), build a
//            per-channel inverted index (linked lists via atomicExch).
//   phase 2: flat vec4 output mapping with incremental (c,s) tracking;
//            chain walks read smem (29cyc LDS); straddle vec4s handled by
//            two predicated walks (channels c, c+1); streaming STG.128
//            (__stcs) keeps the input L2-resident across graph replays.
// Measured: 69.0us kernel, 5.58 TB/s writes-only — HBM streaming-write
// ceiling; traffic is irreducible (dense 380MB output).
__global__ __launch_bounds__(NTHREADS)
void sparse_input_gather_final(const float* __restrict__ in,
                               float* __restrict__ out)
{
    __shared__ float sdata[DATA_F + 4];   // staged [64][121]
    __shared__ int   head[N_CHANNELS];    // chain head per channel (-1 = empty)
    __shared__ int   nxt[N_DENSE];        // next slot in chain

    const int b = blockIdx.x;
    const int t = threadIdx.x;

    const float* __restrict__ row  = in + (size_t)b * ROW_IN;
    const float* __restrict__ data = row + N_DENSE;

    // ---- phase 1: stage data + build inverted index ----
    int my_c = 0;
    if (t < N_DENSE)
        my_c = (int)__ldg(&row[t]);       // in [0, N_CHANNELS) by construction
    if (t < N_CHANNELS) head[t] = -1;

    {
        const float4* __restrict__ src = reinterpret_cast<const float4*>(data);
        float4* __restrict__ dst = reinterpret_cast<float4*>(sdata);
        #pragma unroll
        for (int i = t; i < DATA_F / 4; i += NTHREADS)   // 1936 vec4
            dst[i] = src[i];
    }
    __syncthreads();
    if (t < N_DENSE)
        nxt[t] = atomicExch(&head[my_c], t);
    __syncthreads();

    // ---- phase 2: gather ----
    float4* __restrict__ ovec = reinterpret_cast<float4*>(out + (size_t)b * ROW_OUT);

    // (c, s) for p = 4t; stride NTHREADS vec4 = 1536 floats = 12*121 + 84
    int c = (4 * t) / N_SAMPLES;
    int s = 4 * t - c * N_SAMPLES;

    #pragma unroll 4
    for (int v = t; v < N_VEC; v += NTHREADS) {
        float4 acc = make_float4(0.f, 0.f, 0.f, 0.f);

        if (s <= N_SAMPLES - 4) {
            // fast path: all 4 samples in channel c (~85% of chains empty)
            int d = head[c];
            while (d >= 0) {
                const float* g = sdata + d * N_SAMPLES + s;
                acc.x += g[0];
                acc.y += g[1];
                acc.z += g[2];
                acc.w += g[3];
                d = nxt[d];
            }
        } else {
            // straddle: nA = 121 - s in {1,2,3} samples from c, rest from c+1
            const int nA = N_SAMPLES - s;
            int d = head[c];
            while (d >= 0) {                           // walk A: channel c
                const float* g = sdata + d * N_SAMPLES + s;
                acc.x += g[0];
                if (nA > 1) acc.y += g[1];
                if (nA > 2) acc.z += g[2];
                d = nxt[d];
            }
            int d2 = head[c + 1];
            while (d2 >= 0) {                          // walk B: channel c+1
                const float* g2 = sdata + d2 * N_SAMPLES - nA;  // + j, j in [nA,3]
                if (nA < 2) acc.y += g2[1];
                if (nA < 3) acc.z += g2[2];
                acc.w += g2[3];
                d2 = nxt[d2];
            }
        }
        __stcs(&ovec[v], acc);          // streaming 128-bit store

        // advance (c, s) by 1536 flat elements: c += 12, s += 84, wrap
        s += 84; c += 12;
        if (s >= N_SAMPLES) { s -= N_SAMPLES; c++; }
    }
}

extern "C" void kernel_launch(void* const* d_in, const int* in_sizes, int n_in,
                              void* d_out, int out_size)
{
    const float* in  = (const float*)d_in[0];
    float*       out = (float*)d_out;
    sparse_input_gather_final<<<BATCH, NTHREADS>>>(in, out);
}